// round 2
// baseline (speedup 1.0000x reference)
#include <cuda_runtime.h>
#include <math.h>

#define B_ 16
#define P_ 32768
#define G_ 32
#define C_ 81
#define NSLOTS 64

// ---- device scratch / accumulators (no dynamic allocation allowed) ----
__device__ double g_match_slots[NSLOTS];
__device__ double g_loc_slots[NSLOTS];
__device__ double g_nomatch;
__device__ int    g_total[B_];
__device__ float  g_scratch[B_ * P_];   // per-row: -1 if matched, else sm_max

// ---------------------------------------------------------------------
__global__ void init_kernel() {
    int t = threadIdx.x;
    if (t < NSLOTS) { g_match_slots[t] = 0.0; g_loc_slots[t] = 0.0; }
    if (t < B_)     g_total[t] = 0;
    if (t == 0)     g_nomatch = 0.0;
}

// ---------------------------------------------------------------------
// One warp per prediction row. 8 warps / block.
__global__ __launch_bounds__(256) void main_kernel(
    const float4* __restrict__ pred_boxes,   // [B*P] float4
    const float*  __restrict__ conf,         // [B*P, C]
    const float4* __restrict__ gt_boxes,     // [B*G] float4
    const int*    __restrict__ gt_labels)    // [B*G]
{
    const int wid  = threadIdx.x >> 5;
    const int lane = threadIdx.x & 31;
    const int row  = (blockIdx.x << 3) + wid;   // global row in [0, B*P)
    const int b    = row >> 15;                 // / P_

    __shared__ float4 s_gt[G_];
    __shared__ float  s_ga[G_];
    __shared__ int    s_lab[G_];
    __shared__ double s_ml[8];
    __shared__ double s_ll[8];
    __shared__ int    s_cnt[8];

    if (threadIdx.x < G_) {
        float4 gb = gt_boxes[(b << 5) + threadIdx.x];
        s_gt[threadIdx.x] = gb;
        s_ga[threadIdx.x] = fmaxf(gb.z - gb.x, 0.f) * fmaxf(gb.w - gb.y, 0.f);
        s_lab[threadIdx.x] = gt_labels[(b << 5) + threadIdx.x];
    }
    __syncthreads();

    // ---- log-softmax stats over the 81-class row (coalesced) ----
    const float* crow = conf + (size_t)row * C_;
    float x0 = crow[lane];
    float x1 = crow[lane + 32];
    bool  has2 = lane < (C_ - 64);              // 17 lanes
    float x2 = has2 ? crow[lane + 64] : -3.402823466e38f;

    float m = fmaxf(fmaxf(x0, x1), x2);
    #pragma unroll
    for (int o = 16; o; o >>= 1) m = fmaxf(m, __shfl_xor_sync(0xffffffffu, m, o));

    float s = __expf(x0 - m) + __expf(x1 - m);
    if (has2) s += __expf(x2 - m);
    #pragma unroll
    for (int o = 16; o; o >>= 1) s += __shfl_xor_sync(0xffffffffu, s, o);

    float lse   = m + __logf(s);
    float smmax = 1.0f / s;                     // max softmax = exp(m - lse)

    // ---- IoU: lane g vs this row's box ----
    float4 pb = pred_boxes[row];                // broadcast load
    float4 gb = s_gt[lane];
    float ltx = fmaxf(pb.x, gb.x), lty = fmaxf(pb.y, gb.y);
    float rbx = fminf(pb.z, gb.z), rby = fminf(pb.w, gb.w);
    float inter = fmaxf(rbx - ltx, 0.f) * fmaxf(rby - lty, 0.f);
    float ap    = fmaxf(pb.z - pb.x, 0.f) * fmaxf(pb.w - pb.y, 0.f);
    float uni   = fmaxf(ap + s_ga[lane] - inter, 1e-9f);
    bool matched = inter > 0.5f * uni;          // iou > 0.5

    unsigned bal = __ballot_sync(0xffffffffu, matched);
    float ml = 0.f, ll = 0.f;
    if (bal) {                                  // rare: skip reduce for unmatched rows
        if (matched) {
            ml = __ldg(&crow[s_lab[lane]]) - lse;
            float d, ad, sl = 0.f;
            d = pb.x - gb.x; ad = fabsf(d); sl += (ad < 1.f) ? 0.5f * d * d : ad - 0.5f;
            d = pb.y - gb.y; ad = fabsf(d); sl += (ad < 1.f) ? 0.5f * d * d : ad - 0.5f;
            d = pb.z - gb.z; ad = fabsf(d); sl += (ad < 1.f) ? 0.5f * d * d : ad - 0.5f;
            d = pb.w - gb.w; ad = fabsf(d); sl += (ad < 1.f) ? 0.5f * d * d : ad - 0.5f;
            ll = 0.25f * sl;
        }
        #pragma unroll
        for (int o = 16; o; o >>= 1) {
            ml += __shfl_xor_sync(0xffffffffu, ml, o);
            ll += __shfl_xor_sync(0xffffffffu, ll, o);
        }
    }

    if (lane == 0) {
        g_scratch[row] = bal ? -1.0f : smmax;
        s_ml[wid]  = (double)ml;
        s_ll[wid]  = (double)ll;
        s_cnt[wid] = __popc(bal);
    }
    __syncthreads();

    if (threadIdx.x == 0) {
        double M = 0.0, L = 0.0; int T = 0;
        #pragma unroll
        for (int i = 0; i < 8; i++) { M += s_ml[i]; L += s_ll[i]; T += s_cnt[i]; }
        int slot = blockIdx.x & (NSLOTS - 1);
        if (M != 0.0) atomicAdd(&g_match_slots[slot], M);
        if (L != 0.0) atomicAdd(&g_loc_slots[slot], L);
        if (T)        atomicAdd(&g_total[b], T);
    }
}

// ---------------------------------------------------------------------
// One block per image: exact top-k sum of log1p via 4x8-bit radix select
// on float bits (positive floats are order-isomorphic to their uint bits).
__global__ __launch_bounds__(1024) void select_kernel() {
    const int b    = blockIdx.x;
    const int tid  = threadIdx.x;
    const int wid  = tid >> 5;
    const int lane = tid & 31;

    __shared__ unsigned s_hist[32][256];   // per-warp histograms
    __shared__ unsigned s_tot[256];
    __shared__ unsigned s_bcast[2];        // [prefix, remaining]
    __shared__ int      s_nv;
    __shared__ int      s_k;
    __shared__ int      s_ired[32];
    __shared__ double   s_red[32];

    // Hold only keys in registers; value = __uint_as_float(key).
    unsigned key[32];
    const float* src = g_scratch + b * P_;
    int nv = 0;
    #pragma unroll
    for (int i = 0; i < 32; i++) {
        float f = src[tid + (i << 10)];
        unsigned kk = (f > 0.f) ? __float_as_uint(f) : 0u;  // 0 = invalid (matched row)
        key[i] = kk;
        nv += (kk != 0u);
    }
    #pragma unroll
    for (int o = 16; o; o >>= 1) nv += __shfl_xor_sync(0xffffffffu, nv, o);
    if (lane == 0) s_ired[wid] = nv;
    __syncthreads();
    if (tid == 0) {
        int t = 0;
        for (int i = 0; i < 32; i++) t += s_ired[i];
        s_nv = t;
        long long kraw = 3LL * (long long)g_total[b];
        s_k = (kraw > (long long)t) ? t : (int)kraw;
    }
    __syncthreads();

    const int nvalid = s_nv;
    const int k      = s_k;

    double acc = 0.0;
    if (k > 0) {
        if (k >= nvalid) {
            // keep everything non-negative
            #pragma unroll
            for (int i = 0; i < 32; i++)
                if (key[i]) acc += (double)log1pf(__uint_as_float(key[i]));
        } else {
            unsigned prefix = 0, prefmask = 0;
            int remaining = k;
            for (int pass = 0; pass < 4; pass++) {
                const int shift = 24 - (pass << 3);
                #pragma unroll
                for (int j = 0; j < 8; j++) s_hist[wid][lane + (j << 5)] = 0;
                __syncthreads();
                #pragma unroll
                for (int i = 0; i < 32; i++) {
                    unsigned kk = key[i];
                    if (kk && (kk & prefmask) == prefix)
                        atomicAdd(&s_hist[wid][(kk >> shift) & 255], 1u);
                }
                __syncthreads();
                if (tid < 256) {
                    unsigned t = 0;
                    for (int w = 0; w < 32; w++) t += s_hist[w][tid];
                    s_tot[tid] = t;
                }
                __syncthreads();
                if (tid == 0) {
                    int rem = remaining;
                    int d = 255;
                    for (; d > 0; d--) {
                        int c = (int)s_tot[d];
                        if (c >= rem) break;
                        rem -= c;
                    }
                    s_bcast[0] = prefix | ((unsigned)d << shift);
                    s_bcast[1] = (unsigned)rem;
                }
                __syncthreads();
                prefix    = s_bcast[0];
                remaining = (int)s_bcast[1];
                prefmask |= (0xFFu << shift);
                __syncthreads();
            }
            // strictly-greater values all kept; ties at tau kept 'remaining' times
            #pragma unroll
            for (int i = 0; i < 32; i++)
                if (key[i] > prefix) acc += (double)log1pf(__uint_as_float(key[i]));
            if (tid == 0)
                acc += (double)remaining * (double)log1pf(__uint_as_float(prefix));
        }
    }

    // block reduce (all threads participate; acc==0 where unused)
    #pragma unroll
    for (int o = 16; o; o >>= 1) acc += __shfl_xor_sync(0xffffffffu, acc, o);
    if (lane == 0) s_red[wid] = acc;
    __syncthreads();
    if (tid == 0) {
        double t = 0.0;
        for (int i = 0; i < 32; i++) t += s_red[i];
        if (t != 0.0) atomicAdd(&g_nomatch, t);
    }
}

// ---------------------------------------------------------------------
__global__ void final_kernel(float* __restrict__ out) {
    double M = 0.0, L = 0.0;
    for (int i = 0; i < NSLOTS; i++) { M += g_match_slots[i]; L += g_loc_slots[i]; }
    double conf_loss = -M + g_nomatch;
    out[0] = (float)((conf_loss + L) / (double)g_total[B_ - 1]);
}

// ---------------------------------------------------------------------
extern "C" void kernel_launch(void* const* d_in, const int* in_sizes, int n_in,
                              void* d_out, int out_size) {
    const float4* pb   = (const float4*)d_in[0];   // pred_boxes       [B,P,4]
    const float*  conf = (const float*) d_in[1];   // pred_confidences [B,P,C]
    const float4* gtb  = (const float4*)d_in[2];   // gt_boxes         [B,G,4]
    const int*    gtl  = (const int*)   d_in[3];   // gt_labels        [B,G]
    (void)in_sizes; (void)n_in; (void)out_size;

    init_kernel<<<1, 64>>>();
    main_kernel<<<(B_ * P_) / 8, 256>>>(pb, conf, gtb, gtl);
    select_kernel<<<B_, 1024>>>();
    final_kernel<<<1, 1>>>((float*)d_out);
}

// round 5
// speedup vs baseline: 1.3379x; 1.3379x over previous
#include <cuda_runtime.h>
#include <math.h>
#include <float.h>

#define B_ 16
#define P_ 32768
#define G_ 32
#define C_ 81
#define NSLOTS 64

// ---- device scratch / accumulators (no dynamic allocation allowed) ----
__device__ double g_match_slots[NSLOTS];
__device__ double g_loc_slots[NSLOTS];
__device__ double g_nomatch;
__device__ int    g_total[B_];
__device__ float  g_scratch[B_ * P_];   // per-row: -1 if matched, else sm_max

// ---------------------------------------------------------------------
__global__ void init_kernel() {
    int t = threadIdx.x;
    if (t < NSLOTS) { g_match_slots[t] = 0.0; g_loc_slots[t] = 0.0; }
    if (t < B_)     g_total[t] = 0;
    if (t == 0)     g_nomatch = 0.0;
}

// ---------------------------------------------------------------------
// 8-lane group per prediction row: 4 rows per warp, 32 rows per 256-thread block.
// Shuffle reductions use width=8 so one SHFL instruction serves 4 rows.
__global__ __launch_bounds__(256) void main_kernel(
    const float4* __restrict__ pred_boxes,   // [B*P] float4
    const float*  __restrict__ conf,         // [B*P, C]
    const float4* __restrict__ gt_boxes,     // [B*G] float4
    const int*    __restrict__ gt_labels)    // [B*G]
{
    const int tid  = threadIdx.x;
    const int lane = tid & 31;
    const int j    = lane & 7;          // lane within 8-lane group
    const int grp  = lane >> 3;         // group within warp (0..3)
    const int warp = tid >> 5;          // 0..7
    const int row  = (blockIdx.x << 5) + (warp << 2) + grp;  // 32 rows/block
    const int b    = blockIdx.x >> 10;  // 1024 blocks per image; no block straddles images

    __shared__ float4 s_gt[G_];
    __shared__ float  s_ga[G_];
    __shared__ int    s_lab[G_];
    __shared__ double s_ml[8];
    __shared__ double s_ll[8];
    __shared__ int    s_cnt[8];

    if (tid < G_) {
        float4 gb = gt_boxes[(b << 5) + tid];
        s_gt[tid] = gb;
        s_ga[tid] = fmaxf(gb.z - gb.x, 0.f) * fmaxf(gb.w - gb.y, 0.f);
        s_lab[tid] = gt_labels[(b << 5) + tid];
    }
    __syncthreads();

    // ---- softmax stats: lane j covers elements j, j+8, ..., j+72 (+80 if j==0) ----
    const float* crow = conf + (size_t)row * C_;
    float x[10];
    #pragma unroll
    for (int i = 0; i < 10; i++) x[i] = crow[j + (i << 3)];
    float x10 = (j == 0) ? crow[80] : -FLT_MAX;

    float m = x10;
    #pragma unroll
    for (int i = 0; i < 10; i++) m = fmaxf(m, x[i]);
    #pragma unroll
    for (int o = 4; o; o >>= 1) m = fmaxf(m, __shfl_xor_sync(0xffffffffu, m, o, 8));

    float s = 0.f;
    #pragma unroll
    for (int i = 0; i < 10; i++) s += __expf(x[i] - m);
    if (j == 0) s += __expf(x10 - m);
    #pragma unroll
    for (int o = 4; o; o >>= 1) s += __shfl_xor_sync(0xffffffffu, s, o, 8);

    float lse   = m + __logf(s);
    float smmax = 1.0f / s;             // max softmax = exp(m - lse)

    // ---- IoU: lane j vs GTs j*4 .. j*4+3 ----
    float4 pb = pred_boxes[row];        // broadcast within group
    float ap = fmaxf(pb.z - pb.x, 0.f) * fmaxf(pb.w - pb.y, 0.f);

    int   mycnt = 0;
    bool  anym  = false;
    float ml = 0.f, ll = 0.f;
    #pragma unroll
    for (int t = 0; t < 4; t++) {
        int g = (j << 2) + t;
        float4 gb = s_gt[g];
        float iw = fminf(pb.z, gb.z) - fmaxf(pb.x, gb.x);
        float ih = fminf(pb.w, gb.w) - fmaxf(pb.y, gb.y);
        float inter = fmaxf(iw, 0.f) * fmaxf(ih, 0.f);
        float uni   = fmaxf(ap + s_ga[g] - inter, 1e-9f);
        if (inter > 0.5f * uni) {       // iou > 0.5
            mycnt++;
            anym = true;
            ml += __ldg(crow + s_lab[g]) - lse;
            float d, ad, sl = 0.f;
            d = pb.x - gb.x; ad = fabsf(d); sl += (ad < 1.f) ? 0.5f * d * d : ad - 0.5f;
            d = pb.y - gb.y; ad = fabsf(d); sl += (ad < 1.f) ? 0.5f * d * d : ad - 0.5f;
            d = pb.z - gb.z; ad = fabsf(d); sl += (ad < 1.f) ? 0.5f * d * d : ad - 0.5f;
            d = pb.w - gb.w; ad = fabsf(d); sl += (ad < 1.f) ? 0.5f * d * d : ad - 0.5f;
            ll += 0.25f * sl;
        }
    }

    unsigned anyb = __ballot_sync(0xffffffffu, anym);
    unsigned grp_any = (anyb >> (grp << 3)) & 0xFFu;

    if (j == 0) g_scratch[row] = grp_any ? -1.0f : smmax;

    int cnt = 0;
    if (anyb) {                         // rare: warps containing any matched row
        cnt = mycnt;
        #pragma unroll
        for (int o = 16; o; o >>= 1) {
            ml  += __shfl_xor_sync(0xffffffffu, ml, o);
            ll  += __shfl_xor_sync(0xffffffffu, ll, o);
            cnt += __shfl_xor_sync(0xffffffffu, cnt, o);
        }
    }

    if (lane == 0) {
        s_ml[warp]  = anyb ? (double)ml : 0.0;
        s_ll[warp]  = anyb ? (double)ll : 0.0;
        s_cnt[warp] = cnt;
    }
    __syncthreads();

    if (tid == 0) {
        double M = 0.0, L = 0.0; int T = 0;
        #pragma unroll
        for (int i = 0; i < 8; i++) { M += s_ml[i]; L += s_ll[i]; T += s_cnt[i]; }
        int slot = blockIdx.x & (NSLOTS - 1);
        if (M != 0.0) atomicAdd(&g_match_slots[slot], M);
        if (L != 0.0) atomicAdd(&g_loc_slots[slot], L);
        if (T)        atomicAdd(&g_total[b], T);
    }
}

// ---------------------------------------------------------------------
// One block per image: exact top-k sum of log1p via MSB-first bitwise
// threshold search on float bits (positive floats order-isomorphic to uint
// bits; all keys <= 0x3F800000 so bits 31..30 are 0). No atomics, no
// histograms: each step is register compares + shuffle sum + 32-entry smem sum.
__global__ __launch_bounds__(1024) void select_kernel() {
    const int b    = blockIdx.x;
    const int tid  = threadIdx.x;
    const int wid  = tid >> 5;
    const int lane = tid & 31;

    __shared__ int      s_warp[32];
    __shared__ unsigned s_prefix;
    __shared__ int      s_nv;
    __shared__ int      s_k;
    __shared__ double   s_red[32];

    unsigned key[32];
    const float* src = g_scratch + b * P_;
    int nv = 0;
    #pragma unroll
    for (int i = 0; i < 32; i++) {
        float f = src[tid + (i << 10)];
        unsigned kk = (f > 0.f) ? __float_as_uint(f) : 0u;  // 0 = matched row
        key[i] = kk;
        nv += (kk != 0u);
    }
    #pragma unroll
    for (int o = 16; o; o >>= 1) nv += __shfl_xor_sync(0xffffffffu, nv, o);
    if (lane == 0) s_warp[wid] = nv;
    __syncthreads();
    if (tid == 0) {
        int t = 0;
        #pragma unroll
        for (int i = 0; i < 32; i++) t += s_warp[i];
        s_nv = t;
        int kraw = 3 * g_total[b];
        s_k = (kraw > t) ? t : kraw;
    }
    __syncthreads();
    const int nvtot = s_nv;
    const int k     = s_k;

    double acc = 0.0;
    if (k > 0) {
        if (k >= nvtot) {
            #pragma unroll
            for (int i = 0; i < 32; i++)
                if (key[i]) acc += (double)log1pf(__uint_as_float(key[i]));
        } else {
            unsigned prefix = 0u;
            for (int bit = 29; bit >= 0; --bit) {
                unsigned cand = prefix | (1u << bit);
                int c = 0;
                #pragma unroll
                for (int i = 0; i < 32; i++) c += (key[i] >= cand);
                #pragma unroll
                for (int o = 16; o; o >>= 1) c += __shfl_xor_sync(0xffffffffu, c, o);
                if (lane == 0) s_warp[wid] = c;
                __syncthreads();
                if (tid == 0) {
                    int t = 0;
                    #pragma unroll
                    for (int w = 0; w < 32; w++) t += s_warp[w];
                    s_prefix = (t >= k) ? cand : prefix;
                }
                __syncthreads();
                prefix = s_prefix;
            }
            // tau = prefix: count(>=tau) >= k > count(>=tau+1). Keep all keys > tau,
            // plus (k - count_gt) copies of tau itself.
            int cgt = 0;
            #pragma unroll
            for (int i = 0; i < 32; i++) cgt += (key[i] > prefix);
            #pragma unroll
            for (int o = 16; o; o >>= 1) cgt += __shfl_xor_sync(0xffffffffu, cgt, o);
            if (lane == 0) s_warp[wid] = cgt;
            __syncthreads();
            #pragma unroll
            for (int i = 0; i < 32; i++)
                if (key[i] > prefix) acc += (double)log1pf(__uint_as_float(key[i]));
            if (tid == 0) {
                int t = 0;
                #pragma unroll
                for (int w = 0; w < 32; w++) t += s_warp[w];
                acc += (double)(k - t) * (double)log1pf(__uint_as_float(prefix));
            }
        }
    }

    // block reduce acc
    #pragma unroll
    for (int o = 16; o; o >>= 1) acc += __shfl_xor_sync(0xffffffffu, acc, o);
    if (lane == 0) s_red[wid] = acc;
    __syncthreads();
    if (tid == 0) {
        double t = 0.0;
        #pragma unroll
        for (int i = 0; i < 32; i++) t += s_red[i];
        if (t != 0.0) atomicAdd(&g_nomatch, t);
    }
}

// ---------------------------------------------------------------------
__global__ void final_kernel(float* __restrict__ out) {
    int lane = threadIdx.x;                       // 32 threads
    double M = g_match_slots[lane] + g_match_slots[lane + 32];
    double L = g_loc_slots[lane]   + g_loc_slots[lane + 32];
    double v = L - M;
    #pragma unroll
    for (int o = 16; o; o >>= 1) v += __shfl_xor_sync(0xffffffffu, v, o);
    if (lane == 0)
        out[0] = (float)((v + g_nomatch) / (double)g_total[B_ - 1]);
}

// ---------------------------------------------------------------------
extern "C" void kernel_launch(void* const* d_in, const int* in_sizes, int n_in,
                              void* d_out, int out_size) {
    const float4* pb   = (const float4*)d_in[0];   // pred_boxes       [B,P,4]
    const float*  conf = (const float*) d_in[1];   // pred_confidences [B,P,C]
    const float4* gtb  = (const float4*)d_in[2];   // gt_boxes         [B,G,4]
    const int*    gtl  = (const int*)   d_in[3];   // gt_labels        [B,G]
    (void)in_sizes; (void)n_in; (void)out_size;

    init_kernel<<<1, 64>>>();
    main_kernel<<<(B_ * P_) / 32, 256>>>(pb, conf, gtb, gtl);
    select_kernel<<<B_, 1024>>>();
    final_kernel<<<1, 32>>>((float*)d_out);
}